// round 7
// baseline (speedup 1.0000x reference)
#include <cuda_runtime.h>

// MakeCutouts: 64 cutouts of [4,3,512,512] fp32 -> bilinear 224x224, out [256,3,224,224].
//
// Vectorized tap-pair gather: the two horizontal taps (ix0, ix0+1) are adjacent
// pixels, so ONE aligned float2 load at (c0 & ~1) plus a lane shuffle replaces
// two scalar gathers per source row -> ~0.57x L1TEX wavefronts vs the flat
// 4-LDG kernel, with no cross-iteration dependence (unlike the R6 row-reuse walk).
//
//   c0 even: taps = (va.x, va.y)
//   c0 odd : taps = (va.y, shfl_down(va.x))   [neighbor base == c0+1 for steps 1,2]
//   fixup (rare: lane 31, or neighbor step >= 3 which needs scale>2): scalar load x[c1]
//   clamp case ix1==ix0 only happens when fx==0 -> tap1 weight is 0, value don't-care.
//
// Warp = 32 consecutive j in one output row (OPLANE, S multiples of 32) -> shuffles
// stay in-row and stores are fully coalesced. Streaming stores keep the 12.6MB
// input (64x reuse) L2-resident against the 154MB output stream.

#define IMG   512
#define S     224
#define CUTN  64
#define NCH   12
#define PLANE (IMG*IMG)
#define OPLANE (S*S)
#define TOTAL (CUTN*OPLANE)
#define TPB   256

__global__ __launch_bounds__(TPB, 4)
void make_cutouts_kernel(const float* __restrict__ x,
                         const int*   __restrict__ sizes,
                         const int*   __restrict__ offsetx,
                         const int*   __restrict__ offsety,
                         float*       __restrict__ out)
{
    const int g   = blockIdx.x * TPB + threadIdx.x;   // exact grid, no bounds check
    const int n   = g / OPLANE;
    const int rem = g - n * OPLANE;
    const int i   = rem / S;
    const int j   = rem - i * S;

    const int   size  = __ldg(sizes + n);
    const float scale = (float)size * (1.0f / (float)S);
    const int   ox    = __ldg(offsetx + n);
    const int   oy    = __ldg(offsety + n);
    const int   sm1   = size - 1;

    // y (source rows)
    float srcy = fmaxf(scale * ((float)i + 0.5f) - 0.5f, 0.0f);
    int   iy0  = (int)floorf(srcy);
    const float fy = srcy - (float)iy0;
    iy0 = min(iy0, sm1);
    const int iy1 = min(iy0 + 1, sm1);

    // x (source cols)
    float srcx = fmaxf(scale * ((float)j + 0.5f) - 0.5f, 0.0f);
    int   ix0  = (int)floorf(srcx);
    const float fx = srcx - (float)ix0;
    ix0 = min(ix0, sm1);
    const int ix1 = min(ix0 + 1, sm1);

    const int  c0  = ox + ix0;
    const int  c1  = ox + ix1;            // clamped; used by fixup path
    const int  b0  = c0 & ~1;             // 8B-aligned float2 base (row base is 2KB-aligned)
    const bool odd = (c0 & 1) != 0;

    // Does neighbor lane's float2 contain x[c0+1]? Its base is (c0+step)&~1 which
    // equals c0+1 for steps 1,2 (c0 odd). step>=3 (scale>2 only) or lane 31 -> fixup.
    const int lane = threadIdx.x & 31;
    const int nc0  = __shfl_down_sync(0xffffffffu, c0, 1);
    const bool need_fix = odd && ((lane == 31) || (nc0 - c0 >= 3));

    const int r0 = (oy + iy0) * IMG;
    const int r1 = (oy + iy1) * IMG;

    const float wy1 = fy, wy0 = 1.0f - fy;
    const float wx1 = fx, wx0 = 1.0f - fx;

    int obase = n * NCH * OPLANE + rem;

    #pragma unroll
    for (int bc = 0; bc < NCH; ++bc) {
        const float* __restrict__ xp = x + bc * PLANE;

        const float2 va = __ldg((const float2*)(xp + r0 + b0));
        const float2 vb = __ldg((const float2*)(xp + r1 + b0));

        const float nxa = __shfl_down_sync(0xffffffffu, va.x, 1);
        const float nxb = __shfl_down_sync(0xffffffffu, vb.x, 1);

        float a0  = odd ? va.y : va.x;    // x[r0, c0]
        float a1  = odd ? nxa  : va.y;    // x[r0, c0+1]
        float b0v = odd ? vb.y : vb.x;    // x[r1, c0]
        float b1v = odd ? nxb  : vb.y;    // x[r1, c0+1]
        if (need_fix) {                    // rare predicated scalar gathers
            a1  = __ldg(xp + r0 + c1);
            b1v = __ldg(xp + r1 + c1);
        }

        const float h0 = fmaf(a1,  wx1, a0  * wx0);
        const float h1 = fmaf(b1v, wx1, b0v * wx0);
        __stcs(out + obase, fmaf(h1, wy1, h0 * wy0));
        obase += OPLANE;
    }
}

extern "C" void kernel_launch(void* const* d_in, const int* in_sizes, int n_in,
                              void* d_out, int out_size)
{
    const float* x       = (const float*)d_in[0];
    const int*   sizes   = (const int*)d_in[1];
    const int*   offsetx = (const int*)d_in[2];
    const int*   offsety = (const int*)d_in[3];
    float* out = (float*)d_out;

    make_cutouts_kernel<<<TOTAL / TPB, TPB>>>(x, sizes, offsetx, offsety, out);
}

// round 8
// speedup vs baseline: 1.2406x; 1.2406x over previous
#include <cuda_runtime.h>

// MakeCutouts: 64 cutouts of [4,3,512,512] fp32 -> bilinear 224x224, out [256,3,224,224].
//
// Row-reuse, branch-free: thread owns column j and walks CHUNK=8 output rows.
// h(row) = x[row,c0]*wx0 + x[row,c1]*wx1.  Row iy1 is strictly increasing ->
// always freshly loaded; row iy0 equals previous iy1 with P = 2-scale, in which
// case its blend is reused via FSEL (no branch, no shuffle, predicated-off LDGs
// cost zero L1 wavefronts). Cuts gather wavefronts to ~0.84x of the flat kernel
// with R6's serialization/ALU overhead removed.
// Warp = 32 consecutive j -> coalesced streaming stores.

#define IMG   512
#define S     224
#define CUTN  64
#define NCH   12
#define CHUNK 8
#define PLANE (IMG*IMG)
#define OPLANE (S*S)

__global__ __launch_bounds__(S, 4)
void make_cutouts_kernel(const float* __restrict__ x,
                         const int*   __restrict__ sizes,
                         const int*   __restrict__ offsetx,
                         const int*   __restrict__ offsety,
                         float*       __restrict__ out)
{
    const int j  = threadIdx.x;            // output column
    const int i0 = blockIdx.x * CHUNK;     // first output row of this chunk
    const int n  = blockIdx.y;             // cutout

    const int   size  = __ldg(sizes + n);
    const float scale = (float)size * (1.0f / (float)S);
    const int   ox    = __ldg(offsetx + n);
    const int   oy    = __ldg(offsety + n);
    const int   sm1   = size - 1;

    // column taps (fixed for the whole walk)
    float srcx = fmaxf(scale * ((float)j + 0.5f) - 0.5f, 0.0f);
    int   ix0  = (int)floorf(srcx);
    const float fx = srcx - (float)ix0;    // frac before clamp (matches ref)
    ix0 = min(ix0, sm1);
    const int ix1 = min(ix0 + 1, sm1);
    const float wx1 = fx, wx0 = 1.0f - fx;

    const float* __restrict__ pA = x + (ox + ix0);   // tap-0 column base
    const float* __restrict__ pB = x + (ox + ix1);   // tap-1 column base (clamped)

    float h1v[NCH];                        // last blended source row, per plane
    int iy1_prev = -1000000;               // sentinel: first row loads both

    float* __restrict__ op = out + (n * NCH * OPLANE + i0 * S + j);

    #pragma unroll 1
    for (int k = 0; k < CHUNK; ++k) {
        const int i = i0 + k;
        float srcy = fmaxf(scale * ((float)i + 0.5f) - 0.5f, 0.0f);
        int   iy0  = (int)floorf(srcy);
        const float fy = srcy - (float)iy0;
        iy0 = min(iy0, sm1);
        const int iy1 = min(iy0 + 1, sm1);
        const float wy1 = fy, wy0 = 1.0f - fy;

        const bool fresh = (iy0 != iy1_prev);   // warp-uniform
        const int r0 = (oy + iy0) * IMG;
        const int r1 = (oy + iy1) * IMG;

        #pragma unroll
        for (int p = 0; p < NCH; ++p) {
            float h0;
            if (fresh) {                        // predicated loads; off -> 0 wf
                const float t0 = __ldg(pA + r0 + p * PLANE);
                const float t1 = __ldg(pB + r0 + p * PLANE);
                h0 = fmaf(t1, wx1, t0 * wx0);
            } else {
                h0 = h1v[p];                    // FSEL reuse of previous blend
            }
            const float u0 = __ldg(pA + r1 + p * PLANE);
            const float u1 = __ldg(pB + r1 + p * PLANE);
            const float h1 = fmaf(u1, wx1, u0 * wx0);
            h1v[p] = h1;
            __stcs(op + p * OPLANE, fmaf(h1, wy1, h0 * wy0));
        }
        op += S;
        iy1_prev = iy1;
    }
}

extern "C" void kernel_launch(void* const* d_in, const int* in_sizes, int n_in,
                              void* d_out, int out_size)
{
    const float* x       = (const float*)d_in[0];
    const int*   sizes   = (const int*)d_in[1];
    const int*   offsetx = (const int*)d_in[2];
    const int*   offsety = (const int*)d_in[3];
    float* out = (float*)d_out;

    dim3 grid(S / CHUNK, CUTN);    // 28 x 64
    dim3 block(S);                 // 224 threads; warp = 32 consecutive j
    make_cutouts_kernel<<<grid, block>>>(x, sizes, offsetx, offsety, out);
}

// round 9
// speedup vs baseline: 1.2831x; 1.0343x over previous
#include <cuda_runtime.h>

// MakeCutouts: 64 cutouts of [4,3,512,512] fp32 -> bilinear 224x224, out [256,3,224,224].
//
// R8 predicated row-reuse + occupancy/ALU fix:
//  - planes split 6+6 across blockIdx.z -> h1v[6], ~half the live registers,
//    __launch_bounds__(224,5) -> 35 warps/SM (occ ~55% vs 40%).
//  - per row-step, 4 precomputed row pointers; all plane loads use immediate
//    offsets (p*PLANE*4 <= 5.24MB < 8MB imm) -> no per-load address IMADs.
//  - row iy1 always fresh (strictly increasing); row iy0 reused via predicate
//    when it equals previous iy1 (P = 2-scale); predicated-off LDGs cost 0 wf.
//  - warp = 32 consecutive j -> coalesced streaming stores (__stcs) keep the
//    12.6MB input (64x reuse) resident in L2 against the 154MB output stream.

#define IMG   512
#define S     224
#define CUTN  64
#define NCH   12
#define PH    6
#define CHUNK 8
#define PLANE (IMG*IMG)
#define OPLANE (S*S)

__global__ __launch_bounds__(S, 5)
void make_cutouts_kernel(const float* __restrict__ x,
                         const int*   __restrict__ sizes,
                         const int*   __restrict__ offsetx,
                         const int*   __restrict__ offsety,
                         float*       __restrict__ out)
{
    const int j     = threadIdx.x;            // output column
    const int i0    = blockIdx.x * CHUNK;     // first output row of this chunk
    const int n     = blockIdx.y;             // cutout
    const int pbase = blockIdx.z * PH;        // plane half (0 or 6)

    const int   size  = __ldg(sizes + n);
    const float scale = (float)size * (1.0f / (float)S);
    const int   ox    = __ldg(offsetx + n);
    const int   oy    = __ldg(offsety + n);
    const int   sm1   = size - 1;

    // column taps (fixed for the whole walk)
    float srcx = fmaxf(scale * ((float)j + 0.5f) - 0.5f, 0.0f);
    int   ix0  = (int)floorf(srcx);
    const float fx = srcx - (float)ix0;       // frac before clamp (matches ref)
    ix0 = min(ix0, sm1);
    const int ix1 = min(ix0 + 1, sm1);
    const float wx1 = fx, wx0 = 1.0f - fx;

    const float* __restrict__ baseA = x + pbase * PLANE + (ox + ix0);
    const float* __restrict__ baseB = x + pbase * PLANE + (ox + ix1);

    float h1v[PH];                            // last blended source row, per plane
    int iy1_prev = -1000000;                  // sentinel: first row loads both

    float* __restrict__ op = out + ((n * NCH + pbase) * OPLANE + i0 * S + j);

    #pragma unroll 1
    for (int k = 0; k < CHUNK; ++k) {
        const int i = i0 + k;
        float srcy = fmaxf(scale * ((float)i + 0.5f) - 0.5f, 0.0f);
        int   iy0  = (int)floorf(srcy);
        const float fy = srcy - (float)iy0;
        iy0 = min(iy0, sm1);
        const int iy1 = min(iy0 + 1, sm1);
        const float wy1 = fy, wy0 = 1.0f - fy;

        const int r0 = (oy + iy0) * IMG;
        const int r1 = (oy + iy1) * IMG;
        const bool fresh = (iy0 != iy1_prev);     // warp-uniform

        // 4 row pointers; all plane loads below are [ptr + imm]
        const float* __restrict__ a0 = baseA + r0;
        const float* __restrict__ b0 = baseB + r0;
        const float* __restrict__ a1 = baseA + r1;
        const float* __restrict__ b1 = baseB + r1;

        #pragma unroll
        for (int p = 0; p < PH; ++p) {
            float h0;
            if (fresh) {                          // predicated; off -> 0 wavefronts
                h0 = fmaf(__ldg(b0 + p * PLANE), wx1,
                          __ldg(a0 + p * PLANE) * wx0);
            } else {
                h0 = h1v[p];
            }
            const float h1 = fmaf(__ldg(b1 + p * PLANE), wx1,
                                  __ldg(a1 + p * PLANE) * wx0);
            h1v[p] = h1;
            __stcs(op + p * OPLANE, fmaf(h1, wy1, h0 * wy0));
        }
        op += S;
        iy1_prev = iy1;
    }
}

extern "C" void kernel_launch(void* const* d_in, const int* in_sizes, int n_in,
                              void* d_out, int out_size)
{
    const float* x       = (const float*)d_in[0];
    const int*   sizes   = (const int*)d_in[1];
    const int*   offsetx = (const int*)d_in[2];
    const int*   offsety = (const int*)d_in[3];
    float* out = (float*)d_out;

    dim3 grid(S / CHUNK, CUTN, NCH / PH);   // 28 x 64 x 2
    dim3 block(S);                          // 224 threads; warp = 32 consecutive j
    make_cutouts_kernel<<<grid, block>>>(x, sizes, offsetx, offsety, out);
}